// round 13
// baseline (speedup 1.0000x reference)
#include <cuda_runtime.h>

#define B_    4
#define N_    2048
#define INF_  512
#define D_    64
#define H_    8
#define BH_   32
#define NCHUNK 32          // 64 ranks per chunk
#define CHSZ   64

// ---------------- scratch (device globals; no allocation) ----------------
__device__ __align__(16) float g_V[B_ * N_ * D_];            // (b, n, 64)
__device__ float g_Q[BH_ * N_];                              // (b*8+h, n)
__device__ float g_K[BH_ * N_];
__device__ int   g_si[BH_ * N_];                             // sorted index
__device__ float g_e1[BH_ * N_];                             // exp(Qsorted)
__device__ float g_e2[BH_ * N_];                             // exp(0.01*Qsorted)
__device__ __align__(16) float g_part[BH_ * NCHUNK * 128];   // per-chunk partial sums (P,N)
__device__ int   g_bcnt[BH_ * NCHUNK];                       // bucket counts
__device__ __align__(16) float4 g_rec[BH_ * NCHUNK * N_];    // packed rows {i, t, w1, w2}

// ---------------- tf32 helpers -------------------------------------------
__device__ __forceinline__ unsigned f2tf32(float x) {
    unsigned r;
    asm("cvt.rna.tf32.f32 %0, %1;" : "=r"(r) : "f"(x));
    return r;
}
__device__ __forceinline__ void mma_tf32(float c[4],
    unsigned a0, unsigned a1, unsigned a2, unsigned a3,
    unsigned b0, unsigned b1)
{
    asm volatile(
        "mma.sync.aligned.m16n8k8.row.col.f32.tf32.tf32.f32 "
        "{%0,%1,%2,%3}, {%4,%5,%6,%7}, {%8,%9}, {%0,%1,%2,%3};"
        : "+f"(c[0]), "+f"(c[1]), "+f"(c[2]), "+f"(c[3])
        : "r"(a0), "r"(a1), "r"(a2), "r"(a3), "r"(b0), "r"(b1));
}
__device__ __forceinline__ void splitf(float v, float& hi, float& lo) {
    unsigned h = f2tf32(v);
    hi = __uint_as_float(h);
    lo = __uint_as_float(f2tf32(v - hi));
}

// ---------------- Kernel A: tf32 tensor-core V = X@Wv + bv, then Q,K -----
// K-chunk 64, 8 double-buffered ktiles. smem floats:
//   XsH/XsL [2][64][68] = 8704 each, WsH/WsL [2][64][72] = 9216 each, Vs 4160
#define XBUF 4352
#define WBUF 4608
#define SMEMA_BYTES ((2 * 8704 + 2 * 9216 + 4160) * 4)

__global__ void __launch_bounds__(256) kernelA(
    const float* __restrict__ X,  const float* __restrict__ Wv, const float* __restrict__ bv,
    const float* __restrict__ Wq, const float* __restrict__ bq,
    const float* __restrict__ Wk, const float* __restrict__ bk)
{
    extern __shared__ __align__(16) float sm[];
    float* XsH = sm;                 // [2][64][68]
    float* XsL = sm + 8704;
    float* WsH = sm + 17408;         // [2][64][72]
    float* WsL = sm + 26624;
    float* Vs  = sm + 35840;         // [64][65]

    int tid  = threadIdx.x;
    int lane = tid & 31, w = tid >> 5;
    int g = lane >> 2, t = lane & 3;
    int row0 = blockIdx.x * 64;                 // global row over b*N_

    int xr = tid >> 2, xkc = (tid & 3) * 16;    // X: row 0..63, 16 floats
    int wk = tid >> 2, wcc = (tid & 3) * 16;    // W: k 0..63, 16 floats
    const float* Xp = X + (size_t)(row0 + xr) * INF_ + xkc;

    float4 xv[4], wv[4];

    auto load_tile = [&](int kt) {
        int o = kt * 64;
#pragma unroll
        for (int j = 0; j < 4; ++j) {
            xv[j] = *(const float4*)(Xp + o + j * 4);
            wv[j] = *(const float4*)&Wv[(o + wk) * 64 + wcc + j * 4];
        }
    };
    auto store_tile = [&](int buf) {
        int xb = buf * XBUF + xr * 68 + xkc;
        int wb = buf * WBUF + wk * 72 + wcc;
#pragma unroll
        for (int j = 0; j < 4; ++j) {
            float4 h, l;
            splitf(xv[j].x, h.x, l.x); splitf(xv[j].y, h.y, l.y);
            splitf(xv[j].z, h.z, l.z); splitf(xv[j].w, h.w, l.w);
            *(float4*)&XsH[xb + j * 4] = h; *(float4*)&XsL[xb + j * 4] = l;
            splitf(wv[j].x, h.x, l.x); splitf(wv[j].y, h.y, l.y);
            splitf(wv[j].z, h.z, l.z); splitf(wv[j].w, h.w, l.w);
            *(float4*)&WsH[wb + j * 4] = h; *(float4*)&WsL[wb + j * 4] = l;
        }
    };

    load_tile(0);
    store_tile(0);
    __syncthreads();

    int rw  = (w >> 1) * 16;        // warp row base
    int nc0 = (w & 1) * 32;         // warp col base
    float acc[4][4] = {};

#pragma unroll 1
    for (int kt = 0; kt < 8; ++kt) {
        int p = kt & 1;
        int pa = p * XBUF, pw = p * WBUF;
        if (kt < 7) load_tile(kt + 1);
#pragma unroll
        for (int ks = 0; ks < 64; ks += 8) {
            int a0i = pa + (rw + g) * 68 + ks + t;
            int a1i = pa + (rw + g + 8) * 68 + ks + t;
            unsigned ah0 = __float_as_uint(XsH[a0i]);
            unsigned ah1 = __float_as_uint(XsH[a1i]);
            unsigned ah2 = __float_as_uint(XsH[a0i + 4]);
            unsigned ah3 = __float_as_uint(XsH[a1i + 4]);
            unsigned al0 = __float_as_uint(XsL[a0i]);
            unsigned al1 = __float_as_uint(XsL[a1i]);
            unsigned al2 = __float_as_uint(XsL[a0i + 4]);
            unsigned al3 = __float_as_uint(XsL[a1i + 4]);
#pragma unroll
            for (int nt = 0; nt < 4; ++nt) {
                int b0i = pw + (ks + t) * 72 + nc0 + nt * 8 + g;
                unsigned bh0 = __float_as_uint(WsH[b0i]);
                unsigned bh1 = __float_as_uint(WsH[b0i + 288]);   // (ks+t+4)*72
                unsigned bl0 = __float_as_uint(WsL[b0i]);
                unsigned bl1 = __float_as_uint(WsL[b0i + 288]);
                mma_tf32(acc[nt], ah0, ah1, ah2, ah3, bh0, bh1);
                mma_tf32(acc[nt], ah0, ah1, ah2, ah3, bl0, bl1);
                mma_tf32(acc[nt], al0, al1, al2, al3, bh0, bh1);
            }
        }
        if (kt < 7) {
            store_tile((kt + 1) & 1);
            __syncthreads();
        }
    }

    // epilogue: acc -> Vs (+bias)
#pragma unroll
    for (int nt = 0; nt < 4; ++nt) {
        int col = nc0 + nt * 8 + 2 * t;
        float bvl0 = bv[col], bvl1 = bv[col + 1];
        Vs[(rw + g)     * 65 + col]     = acc[nt][0] + bvl0;
        Vs[(rw + g)     * 65 + col + 1] = acc[nt][1] + bvl1;
        Vs[(rw + g + 8) * 65 + col]     = acc[nt][2] + bvl0;
        Vs[(rw + g + 8) * 65 + col + 1] = acc[nt][3] + bvl1;
    }
    __syncthreads();

    // write V
    for (int id = tid; id < 64 * 16; id += 256) {
        int r = id >> 4, fq = (id & 15) * 4;
        float4 v = make_float4(Vs[r * 65 + fq], Vs[r * 65 + fq + 1],
                               Vs[r * 65 + fq + 2], Vs[r * 65 + fq + 3]);
        *(float4*)&g_V[(size_t)(row0 + r) * 64 + fq] = v;
    }

    // Q, K projections
    int bb_ = row0 >> 11;               // batch
    int n0  = row0 & (N_ - 1);
    int r   = tid >> 2;
    int hp  = (tid & 3) * 2;
    float q0 = bq[hp], q1 = bq[hp + 1];
    float k0 = bk[hp], k1 = bk[hp + 1];
#pragma unroll 8
    for (int f = 0; f < 64; ++f) {
        float v = Vs[r * 65 + f];
        q0 += v * Wq[f * 8 + hp]; q1 += v * Wq[f * 8 + hp + 1];
        k0 += v * Wk[f * 8 + hp]; k1 += v * Wk[f * 8 + hp + 1];
    }
    int n = n0 + r;
    g_Q[(bb_ * 8 + hp) * N_ + n]     = q0;
    g_Q[(bb_ * 8 + hp + 1) * N_ + n] = q1;
    g_K[(bb_ * 8 + hp) * N_ + n]     = k0;
    g_K[(bb_ * 8 + hp + 1) * N_ + n] = k1;
}

// ------------- Kernel B1: sort + prefix tables + per-row records ---------
#define B1_SMEM_BYTES ((6 * 2048 + 1024 + 32 + 128 + 128 + 32 + 2) * 4)

__device__ __forceinline__ unsigned f2u_order(float f) {
    unsigned u = __float_as_uint(f);
    return u ^ ((u >> 31) ? 0xFFFFFFFFu : 0x80000000u);
}

__global__ void __launch_bounds__(1024) kernelB1()
{
    extern __shared__ __align__(16) char smemRaw[];
    unsigned* key   = (unsigned*)smemRaw;
    int*      idx   = (int*)(key + 2048);
    unsigned* key2  = (unsigned*)(idx + 2048);
    int*      idx2  = (int*)(key2 + 2048);
    float*    e1    = (float*)(idx2 + 2048);
    float*    e2    = e1 + 2048;
    int*      cnt   = (int*)(e2 + 2048);      // [16][64] digit-major
    int*      wsum  = cnt + 1024;             // 32
    float*    c1    = (float*)(wsum + 32);    // 128
    float*    c2    = c1 + 128;
    int*      bcnt  = (int*)(c2 + 128);       // 32
    float*    tots  = (float*)(bcnt + 32);    // 2
    float*    pe1s  = (float*)key2;           // reuse after sort
    float*    pe2s  = (float*)idx2;

    int bh = blockIdx.x;
    int tid = threadIdx.x;
    int lane = tid & 31;
    unsigned ltmask = (lane == 0) ? 0u : (0xFFFFFFFFu >> (32 - lane));

    for (int r = tid; r < N_; r += 1024) {
        key[r] = f2u_order(g_Q[bh * N_ + r]);
        idx[r] = r;
    }
    __syncthreads();

    unsigned* kin = key;  unsigned* kout = key2;
    int*      iin = idx;  int*      iout = idx2;
    int lw0 = tid >> 5, lw1 = 32 + (tid >> 5);
#pragma unroll
    for (int pass = 0; pass < 8; ++pass) {
        int shift = pass * 4;
        cnt[tid] = 0;
        __syncthreads();

        unsigned k0 = kin[tid], k1 = kin[tid + 1024];
        int      i0 = iin[tid], i1 = iin[tid + 1024];
        int d0 = (k0 >> shift) & 15, d1 = (k1 >> shift) & 15;

        unsigned m0 = __match_any_sync(0xFFFFFFFFu, d0);
        unsigned m1 = __match_any_sync(0xFFFFFFFFu, d1);
        int r0 = __popc(m0 & ltmask);
        int r1 = __popc(m1 & ltmask);
        if (r0 == 0) cnt[d0 * 64 + lw0] = __popc(m0);
        if (r1 == 0) cnt[d1 * 64 + lw1] = __popc(m1);
        __syncthreads();

        int v = cnt[tid];
        int inc = v;
#pragma unroll
        for (int off = 1; off < 32; off <<= 1) {
            int nn = __shfl_up_sync(0xFFFFFFFFu, inc, off);
            if (lane >= off) inc += nn;
        }
        if (lane == 31) wsum[tid >> 5] = inc;
        __syncthreads();
        if (tid < 32) {
            int wv = wsum[tid];
            int winc = wv;
#pragma unroll
            for (int off = 1; off < 32; off <<= 1) {
                int nn = __shfl_up_sync(0xFFFFFFFFu, winc, off);
                if (tid >= off) winc += nn;
            }
            wsum[tid] = winc - wv;   // exclusive
        }
        __syncthreads();
        cnt[tid] = inc - v + wsum[tid >> 5];   // exclusive global offset
        __syncthreads();

        int p0 = cnt[d0 * 64 + lw0] + r0;
        int p1 = cnt[d1 * 64 + lw1] + r1;
        kout[p0] = k0; iout[p0] = i0;
        kout[p1] = k1; iout[p1] = i1;
        __syncthreads();
        unsigned* tk = kin; kin = kout; kout = tk;
        int*      ti = iin; iin = iout; iout = ti;
    }

    for (int r = tid; r < N_; r += 1024) {
        unsigned u = key[r];
        float q = __uint_as_float(u ^ ((u >> 31) ? 0x80000000u : 0xFFFFFFFFu));
        float x1 = __expf(q), x2 = __expf(0.01f * q);
        e1[r] = x1; e2[r] = x2;
        g_si[bh * N_ + r] = idx[r];
        g_e1[bh * N_ + r] = x1;
        g_e2[bh * N_ + r] = x2;
    }
    __syncthreads();

    if (tid < 128) {
        float s1 = 0.f, s2 = 0.f;
        for (int q = 0; q < 16; ++q) { s1 += e1[tid * 16 + q]; s2 += e2[tid * 16 + q]; }
        c1[tid] = s1; c2[tid] = s2;
    }
    if (tid >= 128 && tid < 128 + NCHUNK) bcnt[tid - 128] = 0;
    __syncthreads();
    if (tid == 0) {
        float r1 = 0.f, r2 = 0.f;
        for (int q = 0; q < 128; ++q) {
            float t1 = c1[q], t2 = c2[q];
            c1[q] = r1; c2[q] = r2;
            r1 += t1; r2 += t2;
        }
        tots[0] = r1; tots[1] = r2;
    }
    __syncthreads();
    if (tid < 128) {
        float r1 = c1[tid], r2 = c2[tid];
        for (int q = 0; q < 16; ++q) {
            int r = tid * 16 + q;
            pe1s[r] = r1; pe2s[r] = r2;
            r1 += e1[r]; r2 += e2[r];
        }
    }
    __syncthreads();

    float tote1 = tots[0], tote2 = tots[1];

    for (int i = tid; i < N_; i += 1024) {
        float kv = g_K[bh * N_ + i];
        unsigned tu = f2u_order(-kv);
        int lo = 0, hi = N_;
        while (lo < hi) {
            int mid = (lo + hi) >> 1;
            if (key[mid] <= tu) lo = mid + 1; else hi = mid;
        }
        float pe1 = (lo < N_) ? pe1s[lo] : tote1;
        float pe2 = (lo < N_) ? pe2s[lo] : tote2;
        float ek  = __expf(kv);
        float ek2 = __expf(0.01f * kv);
        float inv = 1.0f / (ek * (tote1 - pe1) + ek2 * pe2);
        int c = lo >> 6; if (c > NCHUNK - 1) c = NCHUNK - 1;   // t==2048 -> chunk 31
        int pos = atomicAdd(&bcnt[c], 1);
        g_rec[(bh * NCHUNK + c) * N_ + pos] =
            make_float4(__int_as_float(i), __int_as_float(lo), ek * inv, ek2 * inv);
    }
    __syncthreads();
    if (tid < NCHUNK) g_bcnt[bh * NCHUNK + tid] = bcnt[tid];
}

// ------------- Kernel P: weighted V partial sums (8 chunks / CTA) --------
__global__ void __launch_bounds__(256) kernelP()
{
    __shared__ int   sidx[512];
    __shared__ float se1[512], se2[512];

    int blk = blockIdx.x;
    int bh  = blk >> 2;
    int gq  = blk & 3;           // octet of chunks
    int b   = bh >> 3;
    int tid = threadIdx.x;
    int sub = tid >> 5;          // chunk-in-octet 0..7
    int f2  = tid & 31;          // column pair
    int base = gq * 512;

    for (int i = tid; i < 512; i += 256) {
        sidx[i] = g_si[bh * N_ + base + i];
        se1[i]  = g_e1[bh * N_ + base + i];
        se2[i]  = g_e2[bh * N_ + base + i];
    }
    __syncthreads();

    int r0 = sub * 64;
    float p0a = 0.f, n0a = 0.f, p1a = 0.f, n1a = 0.f;
    float p0b = 0.f, n0b = 0.f, p1b = 0.f, n1b = 0.f;
#pragma unroll 8
    for (int r = 0; r < 64; r += 2) {
        float2 va = *(const float2*)&g_V[((size_t)b * N_ + sidx[r0 + r]) * 64 + 2 * f2];
        float e1a = se1[r0 + r], e2a = se2[r0 + r];
        p0a += e1a * va.x; n0a += e2a * va.x;
        p1a += e1a * va.y; n1a += e2a * va.y;
        float2 vb = *(const float2*)&g_V[((size_t)b * N_ + sidx[r0 + r + 1]) * 64 + 2 * f2];
        float e1b = se1[r0 + r + 1], e2b = se2[r0 + r + 1];
        p0b += e1b * vb.x; n0b += e2b * vb.x;
        p1b += e1b * vb.y; n1b += e2b * vb.y;
    }
    int g = gq * 8 + sub;
    *(float4*)&g_part[(bh * NCHUNK + g) * 128 + 4 * f2] =
        make_float4(p0a + p0b, n0a + n0b, p1a + p1b, n1a + n1b);
}

// ------------- Kernel BC: fused cross-chunk scan + smem prefix + output ---
__global__ void __launch_bounds__(256) kernelBC(float* __restrict__ out)
{
    __shared__ __align__(16) float contrib[CHSZ * 128];  // 64 ranks x 128 cols (P,N)
    __shared__ __align__(16) float colEnd[128];
    __shared__ __align__(16) float sTot[128];
    __shared__ float e1s[CHSZ], e2s[CHSZ];
    __shared__ int   sidx[CHSZ];

    int blk = blockIdx.x;
    int bh  = blk >> 5;          // 0..31
    int g   = blk & 31;          // chunk
    int b   = bh >> 3, h = bh & 7;
    int tid = threadIdx.x;
    int r0  = g * CHSZ;

    float cstart = 0.f;
    if (tid < 128) {
        float v[NCHUNK];
#pragma unroll
        for (int gg = 0; gg < NCHUNK; ++gg)
            v[gg] = g_part[(bh * NCHUNK + gg) * 128 + tid];
        float tot = 0.f;
#pragma unroll
        for (int gg = 0; gg < NCHUNK; ++gg) {
            if (gg < g) cstart += v[gg];
            tot += v[gg];
        }
        sTot[tid] = tot;
    }

    if (tid >= 128 && tid < 128 + CHSZ) {
        int l = tid - 128;
        e1s[l]  = g_e1[bh * N_ + r0 + l];
        e2s[l]  = g_e2[bh * N_ + r0 + l];
        sidx[l] = g_si[bh * N_ + r0 + l];
    }
    __syncthreads();

    // gather weighted V rows: float2 loads, one STS.128 per pair
    for (int id = tid; id < CHSZ * 32; id += 256) {
        int r = id >> 5, f2 = id & 31;
        float2 v = *(const float2*)&g_V[((size_t)b * N_ + sidx[r]) * 64 + 2 * f2];
        *(float4*)&contrib[r * 128 + 4 * f2] =
            make_float4(e1s[r] * v.x, e2s[r] * v.x, e1s[r] * v.y, e2s[r] * v.y);
    }
    __syncthreads();

    if (tid < 128) {
        float run = cstart;
#pragma unroll 8
        for (int r = 0; r < CHSZ; ++r) {
            float t = contrib[r * 128 + tid];
            contrib[r * 128 + tid] = run;
            run += t;
        }
        colEnd[tid] = run;
    }
    __syncthreads();

    int base = (bh * NCHUNK + g) * N_;
    int cnt  = g_bcnt[bh * NCHUNK + g];
    int w    = tid >> 5, lane = tid & 31;

    float4 rec = make_float4(0.f, 0.f, 0.f, 0.f);
    if (w < cnt) rec = g_rec[base + w];
    for (int ii = w; ii < cnt; ii += 8) {
        float4 nrec = rec;
        if (ii + 8 < cnt) nrec = g_rec[base + ii + 8];

        int i     = __float_as_int(rec.x);
        int local = __float_as_int(rec.y) - r0;
        const float* row = (local < CHSZ) ? &contrib[local * 128] : colEnd;
        float4 c = *(const float4*)&row[lane * 4];
        float o0 = rec.z * (sTot[lane * 4 + 0] - c.x) + rec.w * c.y;
        float o1 = rec.z * (sTot[lane * 4 + 2] - c.z) + rec.w * c.w;
        *(float2*)&out[((size_t)(b * N_ + i)) * 512 + h * 64 + lane * 2] = make_float2(o0, o1);

        rec = nrec;
    }
}

// ------------- launch -----------------------------------------------------
extern "C" void kernel_launch(void* const* d_in, const int* in_sizes, int n_in,
                              void* d_out, int out_size)
{
    const float* X  = (const float*)d_in[0];
    const float* Wv = (const float*)d_in[1];
    const float* bv = (const float*)d_in[2];
    const float* Wq = (const float*)d_in[3];
    const float* bq = (const float*)d_in[4];
    const float* Wk = (const float*)d_in[5];
    const float* bk = (const float*)d_in[6];

    cudaFuncSetAttribute(kernelA,  cudaFuncAttributeMaxDynamicSharedMemorySize, SMEMA_BYTES);
    cudaFuncSetAttribute(kernelB1, cudaFuncAttributeMaxDynamicSharedMemorySize, B1_SMEM_BYTES);

    kernelA<<<(B_ * N_) / 64, 256, SMEMA_BYTES>>>(X, Wv, bv, Wq, bq, Wk, bk);
    kernelB1<<<BH_, 1024, B1_SMEM_BYTES>>>();
    kernelP<<<BH_ * 4, 256>>>();
    kernelBC<<<BH_ * NCHUNK, 256>>>((float*)d_out);
}

// round 14
// speedup vs baseline: 1.0541x; 1.0541x over previous
#include <cuda_runtime.h>

#define B_    4
#define N_    2048
#define INF_  512
#define D_    64
#define H_    8
#define BH_   32
#define NCHUNK 32          // 64 ranks per chunk
#define CHSZ   64
#define MASK24 0xFFFFFF00u

// ---------------- scratch (device globals; no allocation) ----------------
__device__ __align__(16) float g_V[B_ * N_ * D_];            // (b, n, 64)
__device__ __align__(16) float g_WH[INF_ * D_];              // tf32-hi of Wv
__device__ __align__(16) float g_WL[INF_ * D_];              // tf32-lo of Wv
__device__ float g_Q[BH_ * N_];                              // (b*8+h, n)
__device__ float g_K[BH_ * N_];
__device__ int   g_si[BH_ * N_];                             // sorted index
__device__ float g_e1[BH_ * N_];                             // exp(Qsorted)
__device__ float g_e2[BH_ * N_];                             // exp(0.01*Qsorted)
__device__ __align__(16) float g_part[BH_ * NCHUNK * 128];   // per-chunk partial sums (P,N)
__device__ int   g_bcnt[BH_ * NCHUNK];                       // bucket counts
__device__ __align__(16) float4 g_rec[BH_ * NCHUNK * N_];    // packed rows {i, t, w1, w2}

// ---------------- tf32 helpers -------------------------------------------
__device__ __forceinline__ unsigned f2tf32(float x) {
    unsigned r;
    asm("cvt.rna.tf32.f32 %0, %1;" : "=r"(r) : "f"(x));
    return r;
}
__device__ __forceinline__ void mma_tf32(float c[4],
    unsigned a0, unsigned a1, unsigned a2, unsigned a3,
    unsigned b0, unsigned b1)
{
    asm volatile(
        "mma.sync.aligned.m16n8k8.row.col.f32.tf32.tf32.f32 "
        "{%0,%1,%2,%3}, {%4,%5,%6,%7}, {%8,%9}, {%0,%1,%2,%3};"
        : "+f"(c[0]), "+f"(c[1]), "+f"(c[2]), "+f"(c[3])
        : "r"(a0), "r"(a1), "r"(a2), "r"(a3), "r"(b0), "r"(b1));
}
__device__ __forceinline__ void splitf(float v, float& hi, float& lo) {
    unsigned h = f2tf32(v);
    hi = __uint_as_float(h);
    lo = __uint_as_float(f2tf32(v - hi));
}

// ---------------- Kernel W: pre-split Wv into tf32 hi/lo ------------------
__global__ void __launch_bounds__(256) kernelW(const float* __restrict__ Wv)
{
    int i = blockIdx.x * 256 + threadIdx.x;     // grid 128 -> 32768 elems
    float hi, lo;
    splitf(Wv[i], hi, lo);
    g_WH[i] = hi;
    g_WL[i] = lo;
}

// ---------------- Kernel A: tf32 tensor-core V = X@Wv + bv, then Q,K -----
// Pre-split hi/lo in smem; W already split in global. Inner loop = LDS + MMA.
#define SMEMA_BYTES ((4 * 4608 + 4160) * 4)

__global__ void __launch_bounds__(256) kernelA(
    const float* __restrict__ X,  const float* __restrict__ bv,
    const float* __restrict__ Wq, const float* __restrict__ bq,
    const float* __restrict__ Wk, const float* __restrict__ bk)
{
    extern __shared__ __align__(16) float sm[];
    float* XsH = sm;               // [2][64][36]
    float* XsL = sm + 4608;
    float* WsH = sm + 9216;        // [2][32][72]
    float* WsL = sm + 13824;
    float* Vs  = sm + 18432;       // [64][65]

    int tid  = threadIdx.x;
    int lane = tid & 31, w = tid >> 5;
    int g = lane >> 2, t = lane & 3;
    int row0 = blockIdx.x * 64;                 // global row over b*N_

    int xr = tid >> 2, xk = (tid & 3) * 8;      // X: row 0..63, 8 floats
    int wk = tid >> 3, wc = (tid & 7) * 8;      // W: k 0..31, 8 floats
    const float* Xp = X + (size_t)(row0 + xr) * INF_ + xk;

    float4 xv0, xv1, whv0, whv1, wlv0, wlv1;

    auto store_tile = [&](int buf) {
        int xb = buf * 2304 + xr * 36 + xk;
        int wb = buf * 2304 + wk * 72 + wc;
        float4 h, l;
        splitf(xv0.x, h.x, l.x); splitf(xv0.y, h.y, l.y);
        splitf(xv0.z, h.z, l.z); splitf(xv0.w, h.w, l.w);
        *(float4*)&XsH[xb] = h; *(float4*)&XsL[xb] = l;
        splitf(xv1.x, h.x, l.x); splitf(xv1.y, h.y, l.y);
        splitf(xv1.z, h.z, l.z); splitf(xv1.w, h.w, l.w);
        *(float4*)&XsH[xb + 4] = h; *(float4*)&XsL[xb + 4] = l;
        *(float4*)&WsH[wb]     = whv0; *(float4*)&WsL[wb]     = wlv0;
        *(float4*)&WsH[wb + 4] = whv1; *(float4*)&WsL[wb + 4] = wlv1;
    };

    xv0  = *(const float4*)(Xp);
    xv1  = *(const float4*)(Xp + 4);
    whv0 = *(const float4*)&g_WH[wk * 64 + wc];
    whv1 = *(const float4*)&g_WH[wk * 64 + wc + 4];
    wlv0 = *(const float4*)&g_WL[wk * 64 + wc];
    wlv1 = *(const float4*)&g_WL[wk * 64 + wc + 4];
    store_tile(0);
    __syncthreads();

    int rw  = (w >> 1) * 16;        // warp row base
    int nc0 = (w & 1) * 32;         // warp col base
    float acc[4][4] = {};

#pragma unroll 1
    for (int kt = 0; kt < 16; ++kt) {
        int p = kt & 1, pb = p * 2304;
        if (kt < 15) {
            int o = (kt + 1) * 32;
            xv0  = *(const float4*)(Xp + o);
            xv1  = *(const float4*)(Xp + o + 4);
            whv0 = *(const float4*)&g_WH[(o + wk) * 64 + wc];
            whv1 = *(const float4*)&g_WH[(o + wk) * 64 + wc + 4];
            wlv0 = *(const float4*)&g_WL[(o + wk) * 64 + wc];
            wlv1 = *(const float4*)&g_WL[(o + wk) * 64 + wc + 4];
        }
#pragma unroll
        for (int ks = 0; ks < 32; ks += 8) {
            int a0i = pb + (rw + g) * 36 + ks + t;
            int a1i = pb + (rw + g + 8) * 36 + ks + t;
            unsigned ah0 = __float_as_uint(XsH[a0i]);
            unsigned ah1 = __float_as_uint(XsH[a1i]);
            unsigned ah2 = __float_as_uint(XsH[a0i + 4]);
            unsigned ah3 = __float_as_uint(XsH[a1i + 4]);
            unsigned al0 = __float_as_uint(XsL[a0i]);
            unsigned al1 = __float_as_uint(XsL[a1i]);
            unsigned al2 = __float_as_uint(XsL[a0i + 4]);
            unsigned al3 = __float_as_uint(XsL[a1i + 4]);
#pragma unroll
            for (int nt = 0; nt < 4; ++nt) {
                int b0i = pb + (ks + t) * 72 + nc0 + nt * 8 + g;
                unsigned bh0 = __float_as_uint(WsH[b0i]);
                unsigned bh1 = __float_as_uint(WsH[b0i + 288]);   // (ks+t+4)*72
                unsigned bl0 = __float_as_uint(WsL[b0i]);
                unsigned bl1 = __float_as_uint(WsL[b0i + 288]);
                mma_tf32(acc[nt], ah0, ah1, ah2, ah3, bh0, bh1);
                mma_tf32(acc[nt], ah0, ah1, ah2, ah3, bl0, bl1);
                mma_tf32(acc[nt], al0, al1, al2, al3, bh0, bh1);
            }
        }
        if (kt < 15) {
            store_tile((kt + 1) & 1);
            __syncthreads();
        }
    }

    // epilogue: acc -> Vs (+bias)
#pragma unroll
    for (int nt = 0; nt < 4; ++nt) {
        int col = nc0 + nt * 8 + 2 * t;
        float bvl0 = bv[col], bvl1 = bv[col + 1];
        Vs[(rw + g)     * 65 + col]     = acc[nt][0] + bvl0;
        Vs[(rw + g)     * 65 + col + 1] = acc[nt][1] + bvl1;
        Vs[(rw + g + 8) * 65 + col]     = acc[nt][2] + bvl0;
        Vs[(rw + g + 8) * 65 + col + 1] = acc[nt][3] + bvl1;
    }
    __syncthreads();

    // write V
    for (int id = tid; id < 64 * 16; id += 256) {
        int r = id >> 4, fq = (id & 15) * 4;
        float4 v = make_float4(Vs[r * 65 + fq], Vs[r * 65 + fq + 1],
                               Vs[r * 65 + fq + 2], Vs[r * 65 + fq + 3]);
        *(float4*)&g_V[(size_t)(row0 + r) * 64 + fq] = v;
    }

    // Q, K projections
    int bb_ = row0 >> 11;               // batch
    int n0  = row0 & (N_ - 1);
    int r   = tid >> 2;
    int hp  = (tid & 3) * 2;
    float q0 = bq[hp], q1 = bq[hp + 1];
    float k0 = bk[hp], k1 = bk[hp + 1];
#pragma unroll 8
    for (int f = 0; f < 64; ++f) {
        float v = Vs[r * 65 + f];
        q0 += v * Wq[f * 8 + hp]; q1 += v * Wq[f * 8 + hp + 1];
        k0 += v * Wk[f * 8 + hp]; k1 += v * Wk[f * 8 + hp + 1];
    }
    int n = n0 + r;
    g_Q[(bb_ * 8 + hp) * N_ + n]     = q0;
    g_Q[(bb_ * 8 + hp + 1) * N_ + n] = q1;
    g_K[(bb_ * 8 + hp) * N_ + n]     = k0;
    g_K[(bb_ * 8 + hp + 1) * N_ + n] = k1;
}

// ------------- Kernel B1: 24-bit sort + prefix tables + records ----------
#define B1_SMEM_BYTES ((6 * 2048 + 1024 + 32 + 128 + 128 + 32 + 2) * 4)

__device__ __forceinline__ unsigned f2u_order(float f) {
    unsigned u = __float_as_uint(f);
    return u ^ ((u >> 31) ? 0xFFFFFFFFu : 0x80000000u);
}

__global__ void __launch_bounds__(1024) kernelB1()
{
    extern __shared__ __align__(16) char smemRaw[];
    unsigned* key   = (unsigned*)smemRaw;
    int*      idx   = (int*)(key + 2048);
    unsigned* key2  = (unsigned*)(idx + 2048);
    int*      idx2  = (int*)(key2 + 2048);
    float*    e1    = (float*)(idx2 + 2048);
    float*    e2    = e1 + 2048;
    int*      cnt   = (int*)(e2 + 2048);      // [16][64] digit-major
    int*      wsum  = cnt + 1024;             // 32
    float*    c1    = (float*)(wsum + 32);    // 128
    float*    c2    = c1 + 128;
    int*      bcnt  = (int*)(c2 + 128);       // 32
    float*    tots  = (float*)(bcnt + 32);    // 2
    float*    pe1s  = (float*)key2;           // reuse after sort
    float*    pe2s  = (float*)idx2;

    int bh = blockIdx.x;
    int tid = threadIdx.x;
    int lane = tid & 31;
    unsigned ltmask = (lane == 0) ? 0u : (0xFFFFFFFFu >> (32 - lane));

    for (int r = tid; r < N_; r += 1024) {
        key[r] = f2u_order(g_Q[bh * N_ + r]);
        idx[r] = r;
    }
    __syncthreads();

    // STABLE 4-bit LSD radix sort over bits [8,32): 6 passes (even -> ends in key)
    unsigned* kin = key;  unsigned* kout = key2;
    int*      iin = idx;  int*      iout = idx2;
    int lw0 = tid >> 5, lw1 = 32 + (tid >> 5);
#pragma unroll
    for (int pass = 0; pass < 6; ++pass) {
        int shift = 8 + pass * 4;
        cnt[tid] = 0;
        __syncthreads();

        unsigned k0 = kin[tid], k1 = kin[tid + 1024];
        int      i0 = iin[tid], i1 = iin[tid + 1024];
        int d0 = (k0 >> shift) & 15, d1 = (k1 >> shift) & 15;

        unsigned m0 = __match_any_sync(0xFFFFFFFFu, d0);
        unsigned m1 = __match_any_sync(0xFFFFFFFFu, d1);
        int r0 = __popc(m0 & ltmask);
        int r1 = __popc(m1 & ltmask);
        if (r0 == 0) cnt[d0 * 64 + lw0] = __popc(m0);
        if (r1 == 0) cnt[d1 * 64 + lw1] = __popc(m1);
        __syncthreads();

        int v = cnt[tid];
        int inc = v;
#pragma unroll
        for (int off = 1; off < 32; off <<= 1) {
            int nn = __shfl_up_sync(0xFFFFFFFFu, inc, off);
            if (lane >= off) inc += nn;
        }
        if (lane == 31) wsum[tid >> 5] = inc;
        __syncthreads();
        if (tid < 32) {
            int wv = wsum[tid];
            int winc = wv;
#pragma unroll
            for (int off = 1; off < 32; off <<= 1) {
                int nn = __shfl_up_sync(0xFFFFFFFFu, winc, off);
                if (tid >= off) winc += nn;
            }
            wsum[tid] = winc - wv;   // exclusive
        }
        __syncthreads();
        cnt[tid] = inc - v + wsum[tid >> 5];   // exclusive global offset
        __syncthreads();

        int p0 = cnt[d0 * 64 + lw0] + r0;
        int p1 = cnt[d1 * 64 + lw1] + r1;
        kout[p0] = k0; iout[p0] = i0;
        kout[p1] = k1; iout[p1] = i1;
        __syncthreads();
        unsigned* tk = kin; kin = kout; kout = tk;
        int*      ti = iin; iin = iout; iout = ti;
    }

    // exp tables + publish sorted order (full-precision Q recovered from key)
    for (int r = tid; r < N_; r += 1024) {
        unsigned u = key[r];
        float q = __uint_as_float(u ^ ((u >> 31) ? 0x80000000u : 0xFFFFFFFFu));
        float x1 = __expf(q), x2 = __expf(0.01f * q);
        e1[r] = x1; e2[r] = x2;
        g_si[bh * N_ + r] = idx[r];
        g_e1[bh * N_ + r] = x1;
        g_e2[bh * N_ + r] = x2;
    }
    __syncthreads();

    if (tid < 128) {
        float s1 = 0.f, s2 = 0.f;
        for (int q = 0; q < 16; ++q) { s1 += e1[tid * 16 + q]; s2 += e2[tid * 16 + q]; }
        c1[tid] = s1; c2[tid] = s2;
    }
    if (tid >= 128 && tid < 128 + NCHUNK) bcnt[tid - 128] = 0;
    __syncthreads();
    if (tid == 0) {
        float r1 = 0.f, r2 = 0.f;
        for (int q = 0; q < 128; ++q) {
            float t1 = c1[q], t2 = c2[q];
            c1[q] = r1; c2[q] = r2;
            r1 += t1; r2 += t2;
        }
        tots[0] = r1; tots[1] = r2;
    }
    __syncthreads();
    if (tid < 128) {
        float r1 = c1[tid], r2 = c2[tid];
        for (int q = 0; q < 16; ++q) {
            int r = tid * 16 + q;
            pe1s[r] = r1; pe2s[r] = r2;
            r1 += e1[r]; r2 += e2[r];
        }
    }
    __syncthreads();

    float tote1 = tots[0], tote2 = tots[1];

    // per-row records: rank via MASKED binary search (consistent w/ 24-bit sort)
    for (int i = tid; i < N_; i += 1024) {
        float kv = g_K[bh * N_ + i];
        unsigned tu = f2u_order(-kv) & MASK24;
        int lo = 0, hi = N_;
        while (lo < hi) {
            int mid = (lo + hi) >> 1;
            if ((key[mid] & MASK24) <= tu) lo = mid + 1; else hi = mid;
        }
        float pe1 = (lo < N_) ? pe1s[lo] : tote1;
        float pe2 = (lo < N_) ? pe2s[lo] : tote2;
        float ek  = __expf(kv);
        float ek2 = __expf(0.01f * kv);
        float inv = 1.0f / (ek * (tote1 - pe1) + ek2 * pe2);
        int c = lo >> 6; if (c > NCHUNK - 1) c = NCHUNK - 1;   // t==2048 -> chunk 31
        int pos = atomicAdd(&bcnt[c], 1);
        g_rec[(bh * NCHUNK + c) * N_ + pos] =
            make_float4(__int_as_float(i), __int_as_float(lo), ek * inv, ek2 * inv);
    }
    __syncthreads();
    if (tid < NCHUNK) g_bcnt[bh * NCHUNK + tid] = bcnt[tid];
}

// ------------- Kernel P: weighted V partial sums (8 chunks / CTA) --------
__global__ void __launch_bounds__(256) kernelP()
{
    __shared__ int   sidx[512];
    __shared__ float se1[512], se2[512];

    int blk = blockIdx.x;
    int bh  = blk >> 2;
    int gq  = blk & 3;           // octet of chunks
    int b   = bh >> 3;
    int tid = threadIdx.x;
    int sub = tid >> 5;          // chunk-in-octet 0..7
    int f2  = tid & 31;          // column pair
    int base = gq * 512;

    for (int i = tid; i < 512; i += 256) {
        sidx[i] = g_si[bh * N_ + base + i];
        se1[i]  = g_e1[bh * N_ + base + i];
        se2[i]  = g_e2[bh * N_ + base + i];
    }
    __syncthreads();

    int r0 = sub * 64;
    float p0a = 0.f, n0a = 0.f, p1a = 0.f, n1a = 0.f;
    float p0b = 0.f, n0b = 0.f, p1b = 0.f, n1b = 0.f;
#pragma unroll 8
    for (int r = 0; r < 64; r += 2) {
        float2 va = *(const float2*)&g_V[((size_t)b * N_ + sidx[r0 + r]) * 64 + 2 * f2];
        float e1a = se1[r0 + r], e2a = se2[r0 + r];
        p0a += e1a * va.x; n0a += e2a * va.x;
        p1a += e1a * va.y; n1a += e2a * va.y;
        float2 vb = *(const float2*)&g_V[((size_t)b * N_ + sidx[r0 + r + 1]) * 64 + 2 * f2];
        float e1b = se1[r0 + r + 1], e2b = se2[r0 + r + 1];
        p0b += e1b * vb.x; n0b += e2b * vb.x;
        p1b += e1b * vb.y; n1b += e2b * vb.y;
    }
    int g = gq * 8 + sub;
    *(float4*)&g_part[(bh * NCHUNK + g) * 128 + 4 * f2] =
        make_float4(p0a + p0b, n0a + n0b, p1a + p1b, n1a + n1b);
}

// ------------- Kernel BC: fused cross-chunk scan + smem prefix + output ---
__global__ void __launch_bounds__(256) kernelBC(float* __restrict__ out)
{
    __shared__ __align__(16) float contrib[CHSZ * 128];  // 64 ranks x 128 cols (P,N)
    __shared__ __align__(16) float colEnd[128];
    __shared__ __align__(16) float sTot[128];
    __shared__ float e1s[CHSZ], e2s[CHSZ];
    __shared__ int   sidx[CHSZ];

    int blk = blockIdx.x;
    int bh  = blk >> 5;          // 0..31
    int g   = blk & 31;          // chunk
    int b   = bh >> 3, h = bh & 7;
    int tid = threadIdx.x;
    int r0  = g * CHSZ;

    float cstart = 0.f;
    if (tid < 128) {
        float v[NCHUNK];
#pragma unroll
        for (int gg = 0; gg < NCHUNK; ++gg)
            v[gg] = g_part[(bh * NCHUNK + gg) * 128 + tid];
        float tot = 0.f;
#pragma unroll
        for (int gg = 0; gg < NCHUNK; ++gg) {
            if (gg < g) cstart += v[gg];
            tot += v[gg];
        }
        sTot[tid] = tot;
    }

    if (tid >= 128 && tid < 128 + CHSZ) {
        int l = tid - 128;
        e1s[l]  = g_e1[bh * N_ + r0 + l];
        e2s[l]  = g_e2[bh * N_ + r0 + l];
        sidx[l] = g_si[bh * N_ + r0 + l];
    }
    __syncthreads();

    // gather weighted V rows: float2 loads, one STS.128 per pair
    for (int id = tid; id < CHSZ * 32; id += 256) {
        int r = id >> 5, f2 = id & 31;
        float2 v = *(const float2*)&g_V[((size_t)b * N_ + sidx[r]) * 64 + 2 * f2];
        *(float4*)&contrib[r * 128 + 4 * f2] =
            make_float4(e1s[r] * v.x, e2s[r] * v.x, e1s[r] * v.y, e2s[r] * v.y);
    }
    __syncthreads();

    if (tid < 128) {
        float run = cstart;
#pragma unroll 8
        for (int r = 0; r < CHSZ; ++r) {
            float t = contrib[r * 128 + tid];
            contrib[r * 128 + tid] = run;
            run += t;
        }
        colEnd[tid] = run;
    }
    __syncthreads();

    int base = (bh * NCHUNK + g) * N_;
    int cnt  = g_bcnt[bh * NCHUNK + g];
    int w    = tid >> 5, lane = tid & 31;

    float4 rec = make_float4(0.f, 0.f, 0.f, 0.f);
    if (w < cnt) rec = g_rec[base + w];
    for (int ii = w; ii < cnt; ii += 8) {
        float4 nrec = rec;
        if (ii + 8 < cnt) nrec = g_rec[base + ii + 8];

        int i     = __float_as_int(rec.x);
        int local = __float_as_int(rec.y) - r0;
        const float* row = (local < CHSZ) ? &contrib[local * 128] : colEnd;
        float4 c = *(const float4*)&row[lane * 4];
        float o0 = rec.z * (sTot[lane * 4 + 0] - c.x) + rec.w * c.y;
        float o1 = rec.z * (sTot[lane * 4 + 2] - c.z) + rec.w * c.w;
        *(float2*)&out[((size_t)(b * N_ + i)) * 512 + h * 64 + lane * 2] = make_float2(o0, o1);

        rec = nrec;
    }
}

// ------------- launch -----------------------------------------------------
extern "C" void kernel_launch(void* const* d_in, const int* in_sizes, int n_in,
                              void* d_out, int out_size)
{
    const float* X  = (const float*)d_in[0];
    const float* Wv = (const float*)d_in[1];
    const float* bv = (const float*)d_in[2];
    const float* Wq = (const float*)d_in[3];
    const float* bq = (const float*)d_in[4];
    const float* Wk = (const float*)d_in[5];
    const float* bk = (const float*)d_in[6];

    cudaFuncSetAttribute(kernelA,  cudaFuncAttributeMaxDynamicSharedMemorySize, SMEMA_BYTES);
    cudaFuncSetAttribute(kernelB1, cudaFuncAttributeMaxDynamicSharedMemorySize, B1_SMEM_BYTES);

    kernelW<<<(INF_ * D_) / 256, 256>>>(Wv);
    kernelA<<<(B_ * N_) / 64, 256, SMEMA_BYTES>>>(X, bv, Wq, bq, Wk, bk);
    kernelB1<<<BH_, 1024, B1_SMEM_BYTES>>>();
    kernelP<<<BH_ * 4, 256>>>();
    kernelBC<<<BH_ * NCHUNK, 256>>>((float*)d_out);
}

// round 15
// speedup vs baseline: 1.1368x; 1.0784x over previous
#include <cuda_runtime.h>

#define B_    4
#define N_    2048
#define INF_  512
#define D_    64
#define H_    8
#define BH_   32
#define NCHUNK 32          // 64 ranks per chunk
#define CHSZ   64
#define MASK24 0xFFFFFF00u

// ---------------- scratch (device globals; no allocation) ----------------
__device__ __align__(16) float g_V[B_ * N_ * D_];            // (b, n, 64)
__device__ __align__(16) float g_WH[INF_ * D_];              // tf32-hi of Wv
__device__ __align__(16) float g_WL[INF_ * D_];              // tf32-lo of Wv
__device__ float g_Q[BH_ * N_];                              // (b*8+h, n)
__device__ float g_K[BH_ * N_];
__device__ int   g_si[BH_ * N_];                             // sorted index
__device__ float g_e1[BH_ * N_];                             // exp(Qsorted)
__device__ float g_e2[BH_ * N_];                             // exp(0.01*Qsorted)
__device__ __align__(16) float g_part[BH_ * NCHUNK * 128];   // per-chunk partial sums (P,N)
__device__ int   g_bcnt[BH_ * NCHUNK];                       // bucket counts
__device__ __align__(16) float4 g_rec[BH_ * NCHUNK * N_];    // packed rows {i, t, w1, w2}

// ---------------- tf32 helpers -------------------------------------------
__device__ __forceinline__ unsigned f2tf32(float x) {
    unsigned r;
    asm("cvt.rna.tf32.f32 %0, %1;" : "=r"(r) : "f"(x));
    return r;
}
__device__ __forceinline__ void mma_tf32(float c[4],
    unsigned a0, unsigned a1, unsigned a2, unsigned a3,
    unsigned b0, unsigned b1)
{
    asm volatile(
        "mma.sync.aligned.m16n8k8.row.col.f32.tf32.tf32.f32 "
        "{%0,%1,%2,%3}, {%4,%5,%6,%7}, {%8,%9}, {%0,%1,%2,%3};"
        : "+f"(c[0]), "+f"(c[1]), "+f"(c[2]), "+f"(c[3])
        : "r"(a0), "r"(a1), "r"(a2), "r"(a3), "r"(b0), "r"(b1));
}
__device__ __forceinline__ void splitf(float v, float& hi, float& lo) {
    unsigned h = f2tf32(v);
    hi = __uint_as_float(h);
    lo = __uint_as_float(f2tf32(v - hi));
}

// ---------------- Kernel W: pre-split Wv into tf32 hi/lo ------------------
__global__ void __launch_bounds__(256) kernelW(const float* __restrict__ Wv)
{
    int i = blockIdx.x * 256 + threadIdx.x;     // grid 128 -> 32768 elems
    float hi, lo;
    splitf(Wv[i], hi, lo);
    g_WH[i] = hi;
    g_WL[i] = lo;
}

// ---------------- Kernel A: tf32 tensor-core V = X@Wv + bv, then Q,K -----
#define SMEMA_BYTES ((4 * 4608 + 4160) * 4)

__global__ void __launch_bounds__(256) kernelA(
    const float* __restrict__ X,  const float* __restrict__ bv,
    const float* __restrict__ Wq, const float* __restrict__ bq,
    const float* __restrict__ Wk, const float* __restrict__ bk)
{
    extern __shared__ __align__(16) float sm[];
    float* XsH = sm;               // [2][64][36]
    float* XsL = sm + 4608;
    float* WsH = sm + 9216;        // [2][32][72]
    float* WsL = sm + 13824;
    float* Vs  = sm + 18432;       // [64][65]

    int tid  = threadIdx.x;
    int lane = tid & 31, w = tid >> 5;
    int g = lane >> 2, t = lane & 3;
    int row0 = blockIdx.x * 64;                 // global row over b*N_

    int xr = tid >> 2, xk = (tid & 3) * 8;      // X: row 0..63, 8 floats
    int wk = tid >> 3, wc = (tid & 7) * 8;      // W: k 0..31, 8 floats
    const float* Xp = X + (size_t)(row0 + xr) * INF_ + xk;

    float4 xv0, xv1, whv0, whv1, wlv0, wlv1;

    auto store_tile = [&](int buf) {
        int xb = buf * 2304 + xr * 36 + xk;
        int wb = buf * 2304 + wk * 72 + wc;
        float4 h, l;
        splitf(xv0.x, h.x, l.x); splitf(xv0.y, h.y, l.y);
        splitf(xv0.z, h.z, l.z); splitf(xv0.w, h.w, l.w);
        *(float4*)&XsH[xb] = h; *(float4*)&XsL[xb] = l;
        splitf(xv1.x, h.x, l.x); splitf(xv1.y, h.y, l.y);
        splitf(xv1.z, h.z, l.z); splitf(xv1.w, h.w, l.w);
        *(float4*)&XsH[xb + 4] = h; *(float4*)&XsL[xb + 4] = l;
        *(float4*)&WsH[wb]     = whv0; *(float4*)&WsL[wb]     = wlv0;
        *(float4*)&WsH[wb + 4] = whv1; *(float4*)&WsL[wb + 4] = wlv1;
    };

    xv0  = *(const float4*)(Xp);
    xv1  = *(const float4*)(Xp + 4);
    whv0 = *(const float4*)&g_WH[wk * 64 + wc];
    whv1 = *(const float4*)&g_WH[wk * 64 + wc + 4];
    wlv0 = *(const float4*)&g_WL[wk * 64 + wc];
    wlv1 = *(const float4*)&g_WL[wk * 64 + wc + 4];
    store_tile(0);
    __syncthreads();

    int rw  = (w >> 1) * 16;        // warp row base
    int nc0 = (w & 1) * 32;         // warp col base
    float acc[4][4] = {};

#pragma unroll 1
    for (int kt = 0; kt < 16; ++kt) {
        int p = kt & 1, pb = p * 2304;
        if (kt < 15) {
            int o = (kt + 1) * 32;
            xv0  = *(const float4*)(Xp + o);
            xv1  = *(const float4*)(Xp + o + 4);
            whv0 = *(const float4*)&g_WH[(o + wk) * 64 + wc];
            whv1 = *(const float4*)&g_WH[(o + wk) * 64 + wc + 4];
            wlv0 = *(const float4*)&g_WL[(o + wk) * 64 + wc];
            wlv1 = *(const float4*)&g_WL[(o + wk) * 64 + wc + 4];
        }
#pragma unroll
        for (int ks = 0; ks < 32; ks += 8) {
            int a0i = pb + (rw + g) * 36 + ks + t;
            int a1i = pb + (rw + g + 8) * 36 + ks + t;
            unsigned ah0 = __float_as_uint(XsH[a0i]);
            unsigned ah1 = __float_as_uint(XsH[a1i]);
            unsigned ah2 = __float_as_uint(XsH[a0i + 4]);
            unsigned ah3 = __float_as_uint(XsH[a1i + 4]);
            unsigned al0 = __float_as_uint(XsL[a0i]);
            unsigned al1 = __float_as_uint(XsL[a1i]);
            unsigned al2 = __float_as_uint(XsL[a0i + 4]);
            unsigned al3 = __float_as_uint(XsL[a1i + 4]);
#pragma unroll
            for (int nt = 0; nt < 4; ++nt) {
                int b0i = pb + (ks + t) * 72 + nc0 + nt * 8 + g;
                unsigned bh0 = __float_as_uint(WsH[b0i]);
                unsigned bh1 = __float_as_uint(WsH[b0i + 288]);   // (ks+t+4)*72
                unsigned bl0 = __float_as_uint(WsL[b0i]);
                unsigned bl1 = __float_as_uint(WsL[b0i + 288]);
                mma_tf32(acc[nt], ah0, ah1, ah2, ah3, bh0, bh1);
                mma_tf32(acc[nt], ah0, ah1, ah2, ah3, bl0, bl1);
                mma_tf32(acc[nt], al0, al1, al2, al3, bh0, bh1);
            }
        }
        if (kt < 15) {
            store_tile((kt + 1) & 1);
            __syncthreads();
        }
    }

    // epilogue: acc -> Vs (+bias)
#pragma unroll
    for (int nt = 0; nt < 4; ++nt) {
        int col = nc0 + nt * 8 + 2 * t;
        float bvl0 = bv[col], bvl1 = bv[col + 1];
        Vs[(rw + g)     * 65 + col]     = acc[nt][0] + bvl0;
        Vs[(rw + g)     * 65 + col + 1] = acc[nt][1] + bvl1;
        Vs[(rw + g + 8) * 65 + col]     = acc[nt][2] + bvl0;
        Vs[(rw + g + 8) * 65 + col + 1] = acc[nt][3] + bvl1;
    }
    __syncthreads();

    // write V
    for (int id = tid; id < 64 * 16; id += 256) {
        int r = id >> 4, fq = (id & 15) * 4;
        float4 v = make_float4(Vs[r * 65 + fq], Vs[r * 65 + fq + 1],
                               Vs[r * 65 + fq + 2], Vs[r * 65 + fq + 3]);
        *(float4*)&g_V[(size_t)(row0 + r) * 64 + fq] = v;
    }

    // Q, K projections
    int bb_ = row0 >> 11;               // batch
    int n0  = row0 & (N_ - 1);
    int r   = tid >> 2;
    int hp  = (tid & 3) * 2;
    float q0 = bq[hp], q1 = bq[hp + 1];
    float k0 = bk[hp], k1 = bk[hp + 1];
#pragma unroll 8
    for (int f = 0; f < 64; ++f) {
        float v = Vs[r * 65 + f];
        q0 += v * Wq[f * 8 + hp]; q1 += v * Wq[f * 8 + hp + 1];
        k0 += v * Wk[f * 8 + hp]; k1 += v * Wk[f * 8 + hp + 1];
    }
    int n = n0 + r;
    g_Q[(bb_ * 8 + hp) * N_ + n]     = q0;
    g_Q[(bb_ * 8 + hp + 1) * N_ + n] = q1;
    g_K[(bb_ * 8 + hp) * N_ + n]     = k0;
    g_K[(bb_ * 8 + hp + 1) * N_ + n] = k1;
}

// ------------- Kernel B1: 24-bit sort + prefix tables + records ----------
#define B1_SMEM_BYTES ((6 * 2048 + 1024 + 32 + 128 + 128 + 32 + 2) * 4)

__device__ __forceinline__ unsigned f2u_order(float f) {
    unsigned u = __float_as_uint(f);
    return u ^ ((u >> 31) ? 0xFFFFFFFFu : 0x80000000u);
}

__global__ void __launch_bounds__(1024) kernelB1()
{
    extern __shared__ __align__(16) char smemRaw[];
    unsigned* key   = (unsigned*)smemRaw;
    int*      idx   = (int*)(key + 2048);
    unsigned* key2  = (unsigned*)(idx + 2048);
    int*      idx2  = (int*)(key2 + 2048);
    float*    e1    = (float*)(idx2 + 2048);
    float*    e2    = e1 + 2048;
    int*      cnt   = (int*)(e2 + 2048);      // [16][64] digit-major
    int*      wsum  = cnt + 1024;             // 32
    float*    c1    = (float*)(wsum + 32);    // 128
    float*    c2    = c1 + 128;
    int*      bcnt  = (int*)(c2 + 128);       // 32
    float*    tots  = (float*)(bcnt + 32);    // 2
    float*    pe1s  = (float*)key2;           // reuse after sort
    float*    pe2s  = (float*)idx2;

    int bh = blockIdx.x;
    int tid = threadIdx.x;
    int lane = tid & 31;
    unsigned ltmask = (lane == 0) ? 0u : (0xFFFFFFFFu >> (32 - lane));

    for (int r = tid; r < N_; r += 1024) {
        key[r] = f2u_order(g_Q[bh * N_ + r]);
        idx[r] = r;
    }
    __syncthreads();

    // STABLE 4-bit LSD radix sort over bits [8,32): 6 passes (ends in key)
    unsigned* kin = key;  unsigned* kout = key2;
    int*      iin = idx;  int*      iout = idx2;
    int lw0 = tid >> 5, lw1 = 32 + (tid >> 5);
#pragma unroll
    for (int pass = 0; pass < 6; ++pass) {
        int shift = 8 + pass * 4;
        cnt[tid] = 0;
        __syncthreads();

        unsigned k0 = kin[tid], k1 = kin[tid + 1024];
        int      i0 = iin[tid], i1 = iin[tid + 1024];
        int d0 = (k0 >> shift) & 15, d1 = (k1 >> shift) & 15;

        unsigned m0 = __match_any_sync(0xFFFFFFFFu, d0);
        unsigned m1 = __match_any_sync(0xFFFFFFFFu, d1);
        int r0 = __popc(m0 & ltmask);
        int r1 = __popc(m1 & ltmask);
        if (r0 == 0) cnt[d0 * 64 + lw0] = __popc(m0);
        if (r1 == 0) cnt[d1 * 64 + lw1] = __popc(m1);
        __syncthreads();

        int v = cnt[tid];
        int inc = v;
#pragma unroll
        for (int off = 1; off < 32; off <<= 1) {
            int nn = __shfl_up_sync(0xFFFFFFFFu, inc, off);
            if (lane >= off) inc += nn;
        }
        if (lane == 31) wsum[tid >> 5] = inc;
        __syncthreads();
        if (tid < 32) {
            int wv = wsum[tid];
            int winc = wv;
#pragma unroll
            for (int off = 1; off < 32; off <<= 1) {
                int nn = __shfl_up_sync(0xFFFFFFFFu, winc, off);
                if (tid >= off) winc += nn;
            }
            wsum[tid] = winc - wv;   // exclusive
        }
        __syncthreads();
        cnt[tid] = inc - v + wsum[tid >> 5];   // exclusive global offset
        __syncthreads();

        int p0 = cnt[d0 * 64 + lw0] + r0;
        int p1 = cnt[d1 * 64 + lw1] + r1;
        kout[p0] = k0; iout[p0] = i0;
        kout[p1] = k1; iout[p1] = i1;
        __syncthreads();
        unsigned* tk = kin; kin = kout; kout = tk;
        int*      ti = iin; iin = iout; iout = ti;
    }

    // exp tables + publish sorted order
    for (int r = tid; r < N_; r += 1024) {
        unsigned u = key[r];
        float q = __uint_as_float(u ^ ((u >> 31) ? 0x80000000u : 0xFFFFFFFFu));
        float x1 = __expf(q), x2 = __expf(0.01f * q);
        e1[r] = x1; e2[r] = x2;
        g_si[bh * N_ + r] = idx[r];
        g_e1[bh * N_ + r] = x1;
        g_e2[bh * N_ + r] = x2;
    }
    __syncthreads();

    if (tid < 128) {
        float s1 = 0.f, s2 = 0.f;
        for (int q = 0; q < 16; ++q) { s1 += e1[tid * 16 + q]; s2 += e2[tid * 16 + q]; }
        c1[tid] = s1; c2[tid] = s2;
    }
    if (tid >= 128 && tid < 128 + NCHUNK) bcnt[tid - 128] = 0;
    __syncthreads();
    if (tid == 0) {
        float r1 = 0.f, r2 = 0.f;
        for (int q = 0; q < 128; ++q) {
            float t1 = c1[q], t2 = c2[q];
            c1[q] = r1; c2[q] = r2;
            r1 += t1; r2 += t2;
        }
        tots[0] = r1; tots[1] = r2;
    }
    __syncthreads();
    if (tid < 128) {
        float r1 = c1[tid], r2 = c2[tid];
        for (int q = 0; q < 16; ++q) {
            int r = tid * 16 + q;
            pe1s[r] = r1; pe2s[r] = r2;
            r1 += e1[r]; r2 += e2[r];
        }
    }
    __syncthreads();

    float tote1 = tots[0], tote2 = tots[1];

    // per-row records: rank via MASKED binary search
    for (int i = tid; i < N_; i += 1024) {
        float kv = g_K[bh * N_ + i];
        unsigned tu = f2u_order(-kv) & MASK24;
        int lo = 0, hi = N_;
        while (lo < hi) {
            int mid = (lo + hi) >> 1;
            if ((key[mid] & MASK24) <= tu) lo = mid + 1; else hi = mid;
        }
        float pe1 = (lo < N_) ? pe1s[lo] : tote1;
        float pe2 = (lo < N_) ? pe2s[lo] : tote2;
        float ek  = __expf(kv);
        float ek2 = __expf(0.01f * kv);
        float inv = 1.0f / (ek * (tote1 - pe1) + ek2 * pe2);
        int c = lo >> 6; if (c > NCHUNK - 1) c = NCHUNK - 1;   // t==2048 -> chunk 31
        int pos = atomicAdd(&bcnt[c], 1);
        g_rec[(bh * NCHUNK + c) * N_ + pos] =
            make_float4(__int_as_float(i), __int_as_float(lo), ek * inv, ek2 * inv);
    }
    __syncthreads();
    if (tid < NCHUNK) g_bcnt[bh * NCHUNK + tid] = bcnt[tid];
}

// ------------- Kernel P: per-(bh,chunk) partial sums, row-split ----------
// grid 1024 x 256 thr: thread = (row-group q 0..7, col-pair f2 0..31).
// Each sums 8 rows; fixed-order 8-way smem reduction per column.
__global__ void __launch_bounds__(256) kernelP()
{
    __shared__ int   sidx[CHSZ];
    __shared__ float se1[CHSZ], se2[CHSZ];
    __shared__ __align__(16) float red[8 * 128];   // [group][128 cols]

    int blk = blockIdx.x;        // 1024
    int bh  = blk >> 5;
    int g   = blk & 31;
    int b   = bh >> 3;
    int tid = threadIdx.x;
    int r0  = g * CHSZ;

    if (tid < CHSZ) {
        sidx[tid] = g_si[bh * N_ + r0 + tid];
        se1[tid]  = g_e1[bh * N_ + r0 + tid];
        se2[tid]  = g_e2[bh * N_ + r0 + tid];
    }
    __syncthreads();

    int q  = tid >> 5;           // row-group 0..7
    int f2 = tid & 31;           // column pair
    float p0 = 0.f, n0 = 0.f, p1 = 0.f, n1 = 0.f;
#pragma unroll
    for (int rr = 0; rr < 8; ++rr) {
        int r = q * 8 + rr;
        float2 v = *(const float2*)&g_V[((size_t)b * N_ + sidx[r]) * 64 + 2 * f2];
        float e1v = se1[r], e2v = se2[r];
        p0 += e1v * v.x; n0 += e2v * v.x;
        p1 += e1v * v.y; n1 += e2v * v.y;
    }
    *(float4*)&red[q * 128 + 4 * f2] = make_float4(p0, n0, p1, n1);
    __syncthreads();

    if (tid < 128) {
        float s = red[tid];
#pragma unroll
        for (int qq = 1; qq < 8; ++qq) s += red[qq * 128 + tid];
        g_part[(bh * NCHUNK + g) * 128 + tid] = s;
    }
}

// ------------- Kernel BC: fused cross-chunk scan + smem prefix + output ---
__global__ void __launch_bounds__(256) kernelBC(float* __restrict__ out)
{
    __shared__ __align__(16) float contrib[CHSZ * 128];  // 64 ranks x 128 cols (P,N)
    __shared__ __align__(16) float colEnd[128];
    __shared__ __align__(16) float sTot[128];
    __shared__ float e1s[CHSZ], e2s[CHSZ];
    __shared__ int   sidx[CHSZ];

    int blk = blockIdx.x;
    int bh  = blk >> 5;          // 0..31
    int g   = blk & 31;          // chunk
    int b   = bh >> 3, h = bh & 7;
    int tid = threadIdx.x;
    int r0  = g * CHSZ;

    float cstart = 0.f;
    if (tid < 128) {
        float v[NCHUNK];
#pragma unroll
        for (int gg = 0; gg < NCHUNK; ++gg)
            v[gg] = g_part[(bh * NCHUNK + gg) * 128 + tid];
        float tot = 0.f;
#pragma unroll
        for (int gg = 0; gg < NCHUNK; ++gg) {
            if (gg < g) cstart += v[gg];
            tot += v[gg];
        }
        sTot[tid] = tot;
    }

    if (tid >= 128 && tid < 128 + CHSZ) {
        int l = tid - 128;
        e1s[l]  = g_e1[bh * N_ + r0 + l];
        e2s[l]  = g_e2[bh * N_ + r0 + l];
        sidx[l] = g_si[bh * N_ + r0 + l];
    }
    __syncthreads();

    // gather weighted V rows: float2 loads, one STS.128 per pair
    for (int id = tid; id < CHSZ * 32; id += 256) {
        int r = id >> 5, f2 = id & 31;
        float2 v = *(const float2*)&g_V[((size_t)b * N_ + sidx[r]) * 64 + 2 * f2];
        *(float4*)&contrib[r * 128 + 4 * f2] =
            make_float4(e1s[r] * v.x, e2s[r] * v.x, e1s[r] * v.y, e2s[r] * v.y);
    }
    __syncthreads();

    if (tid < 128) {
        float run = cstart;
#pragma unroll 8
        for (int r = 0; r < CHSZ; ++r) {
            float t = contrib[r * 128 + tid];
            contrib[r * 128 + tid] = run;
            run += t;
        }
        colEnd[tid] = run;
    }
    __syncthreads();

    int base = (bh * NCHUNK + g) * N_;
    int cnt  = g_bcnt[bh * NCHUNK + g];
    int w    = tid >> 5, lane = tid & 31;

    float4 rec = make_float4(0.f, 0.f, 0.f, 0.f);
    if (w < cnt) rec = g_rec[base + w];
    for (int ii = w; ii < cnt; ii += 8) {
        float4 nrec = rec;
        if (ii + 8 < cnt) nrec = g_rec[base + ii + 8];

        int i     = __float_as_int(rec.x);
        int local = __float_as_int(rec.y) - r0;
        const float* row = (local < CHSZ) ? &contrib[local * 128] : colEnd;
        float4 c = *(const float4*)&row[lane * 4];
        float o0 = rec.z * (sTot[lane * 4 + 0] - c.x) + rec.w * c.y;
        float o1 = rec.z * (sTot[lane * 4 + 2] - c.z) + rec.w * c.w;
        *(float2*)&out[((size_t)(b * N_ + i)) * 512 + h * 64 + lane * 2] = make_float2(o0, o1);

        rec = nrec;
    }
}

// ------------- launch -----------------------------------------------------
extern "C" void kernel_launch(void* const* d_in, const int* in_sizes, int n_in,
                              void* d_out, int out_size)
{
    const float* X  = (const float*)d_in[0];
    const float* Wv = (const float*)d_in[1];
    const float* bv = (const float*)d_in[2];
    const float* Wq = (const float*)d_in[3];
    const float* bq = (const float*)d_in[4];
    const float* Wk = (const float*)d_in[5];
    const float* bk = (const float*)d_in[6];

    cudaFuncSetAttribute(kernelA,  cudaFuncAttributeMaxDynamicSharedMemorySize, SMEMA_BYTES);
    cudaFuncSetAttribute(kernelB1, cudaFuncAttributeMaxDynamicSharedMemorySize, B1_SMEM_BYTES);

    kernelW<<<(INF_ * D_) / 256, 256>>>(Wv);
    kernelA<<<(B_ * N_) / 64, 256, SMEMA_BYTES>>>(X, bv, Wq, bq, Wk, bk);
    kernelB1<<<BH_, 1024, B1_SMEM_BYTES>>>();
    kernelP<<<BH_ * NCHUNK, 256>>>();
    kernelBC<<<BH_ * NCHUNK, 256>>>((float*)d_out);
}

// round 16
// speedup vs baseline: 1.2394x; 1.0903x over previous
#include <cuda_runtime.h>
#include <cuda_bf16.h>

#define B_    4
#define N_    2048
#define INF_  512
#define D_    64
#define H_    8
#define BH_   32
#define NCHUNK 32          // 64 ranks per chunk
#define CHSZ   64
#define MASK24 0xFFFFFF00u

// ---------------- scratch (device globals; no allocation) ----------------
__device__ __align__(16) float    g_V[B_ * N_ * D_];         // (b, n, 64)
__device__ __align__(16) unsigned g_WHp[256 * 64];           // bf16x2-hi of Wv (kpair, n)
__device__ __align__(16) unsigned g_WMp[256 * 64];           // bf16x2-mid
__device__ float g_Q[BH_ * N_];                              // (b*8+h, n)
__device__ float g_K[BH_ * N_];
__device__ int   g_si[BH_ * N_];                             // sorted index
__device__ float g_e1[BH_ * N_];                             // exp(Qsorted)
__device__ float g_e2[BH_ * N_];                             // exp(0.01*Qsorted)
__device__ __align__(16) float g_part[BH_ * NCHUNK * 128];   // per-chunk partial sums (P,N)
__device__ int   g_bcnt[BH_ * NCHUNK];                       // bucket counts
__device__ __align__(16) float4 g_rec[BH_ * NCHUNK * N_];    // packed rows {i, t, w1, w2}

// ---------------- bf16 helpers -------------------------------------------
__device__ __forceinline__ void cvt2bf(float a, float b, unsigned& Hp, unsigned& Mp) {
    __nv_bfloat16 ha = __float2bfloat16(a), hb = __float2bfloat16(b);
    float ra = a - __bfloat162float(ha);
    float rb = b - __bfloat162float(hb);
    __nv_bfloat16 ma = __float2bfloat16(ra), mb = __float2bfloat16(rb);
    Hp = ((unsigned)__bfloat16_as_ushort(hb) << 16) | __bfloat16_as_ushort(ha);
    Mp = ((unsigned)__bfloat16_as_ushort(mb) << 16) | __bfloat16_as_ushort(ma);
}
__device__ __forceinline__ void mma_bf16(float c[4],
    unsigned a0, unsigned a1, unsigned a2, unsigned a3,
    unsigned b0, unsigned b1)
{
    asm volatile(
        "mma.sync.aligned.m16n8k16.row.col.f32.bf16.bf16.f32 "
        "{%0,%1,%2,%3}, {%4,%5,%6,%7}, {%8,%9}, {%0,%1,%2,%3};"
        : "+f"(c[0]), "+f"(c[1]), "+f"(c[2]), "+f"(c[3])
        : "r"(a0), "r"(a1), "r"(a2), "r"(a3), "r"(b0), "r"(b1));
}

// ---------------- Kernel W: pre-split Wv into packed bf16 hi/mid ----------
__global__ void __launch_bounds__(256) kernelW(const float* __restrict__ Wv)
{
    int i = blockIdx.x * 256 + threadIdx.x;     // 16384 = 256 kpairs x 64 n
    int kp = i >> 6, n = i & 63;
    float x0 = Wv[(2 * kp) * 64 + n];
    float x1 = Wv[(2 * kp + 1) * 64 + n];
    unsigned Hp, Mp;
    cvt2bf(x0, x1, Hp, Mp);
    g_WHp[i] = Hp;
    g_WMp[i] = Mp;
}

// ---------------- Kernel A: bf16 3-term MMA V = X@Wv + bv, then Q,K ------
// smem u32 layout: XsH [2][64*20]=2560, XsM 2560, WsH [2][16*72]=2304,
// WsM 2304, Vs (float) 4160  -> 13888 u32
#define SMEMA_BYTES (13888 * 4)

__global__ void __launch_bounds__(256) kernelA(
    const float* __restrict__ X,  const float* __restrict__ bv,
    const float* __restrict__ Wq, const float* __restrict__ bq,
    const float* __restrict__ Wk, const float* __restrict__ bk)
{
    extern __shared__ __align__(16) unsigned smu[];
    unsigned* XsH = smu;            // [2][64*20]
    unsigned* XsM = smu + 2560;
    unsigned* WsH = smu + 5120;     // [2][16*72]
    unsigned* WsM = smu + 7424;
    float*    Vs  = (float*)(smu + 9728);   // [64][65]

    int tid  = threadIdx.x;
    int lane = tid & 31, w = tid >> 5;
    int g = lane >> 2, t = lane & 3;
    int row0 = blockIdx.x * 64;                 // global row over b*N_

    int xr = tid >> 2, xq = tid & 3;            // X: row, quarter (8 floats)
    int wkp = tid >> 4, wn4 = (tid & 15) * 4;   // W: kpair 0..15, n-group
    const float* Xp = X + (size_t)(row0 + xr) * INF_ + xq * 8;

    float4 xv0, xv1;
    uint4  wh, wm;

    auto store_tile = [&](int buf) {
        unsigned Hx[4], Mx[4];
        cvt2bf(xv0.x, xv0.y, Hx[0], Mx[0]);
        cvt2bf(xv0.z, xv0.w, Hx[1], Mx[1]);
        cvt2bf(xv1.x, xv1.y, Hx[2], Mx[2]);
        cvt2bf(xv1.z, xv1.w, Hx[3], Mx[3]);
        int xb = buf * 1280 + xr * 20 + xq * 4;
        *(uint4*)&XsH[xb] = make_uint4(Hx[0], Hx[1], Hx[2], Hx[3]);
        *(uint4*)&XsM[xb] = make_uint4(Mx[0], Mx[1], Mx[2], Mx[3]);
        int wb = buf * 1152 + wkp * 72 + wn4;
        *(uint4*)&WsH[wb] = wh;
        *(uint4*)&WsM[wb] = wm;
    };

    xv0 = *(const float4*)(Xp);
    xv1 = *(const float4*)(Xp + 4);
    wh  = *(const uint4*)&g_WHp[wkp * 64 + wn4];
    wm  = *(const uint4*)&g_WMp[wkp * 64 + wn4];
    store_tile(0);
    __syncthreads();

    int rw  = (w >> 1) * 16;        // warp row base
    int nc0 = (w & 1) * 32;         // warp col base
    float acc[4][4] = {};

#pragma unroll 1
    for (int kt = 0; kt < 16; ++kt) {
        int p = kt & 1;
        int pa = p * 1280, pw = p * 1152;
        if (kt < 15) {
            int o = (kt + 1) * 32;
            xv0 = *(const float4*)(Xp + o);
            xv1 = *(const float4*)(Xp + o + 4);
            wh  = *(const uint4*)&g_WHp[((kt + 1) * 16 + wkp) * 64 + wn4];
            wm  = *(const uint4*)&g_WMp[((kt + 1) * 16 + wkp) * 64 + wn4];
        }
#pragma unroll
        for (int s = 0; s < 2; ++s) {
            int ab  = pa + (rw + g) * 20 + s * 8 + t;
            int ab2 = pa + (rw + g + 8) * 20 + s * 8 + t;
            unsigned ah0 = XsH[ab],     ah1 = XsH[ab2];
            unsigned ah2 = XsH[ab + 4], ah3 = XsH[ab2 + 4];
            unsigned am0 = XsM[ab],     am1 = XsM[ab2];
            unsigned am2 = XsM[ab + 4], am3 = XsM[ab2 + 4];
#pragma unroll
            for (int nt = 0; nt < 4; ++nt) {
                int bb = pw + (s * 8 + t) * 72 + nc0 + nt * 8 + g;
                unsigned bh0 = WsH[bb], bh1 = WsH[bb + 288];   // (t+4)*72
                unsigned bm0 = WsM[bb], bm1 = WsM[bb + 288];
                mma_bf16(acc[nt], ah0, ah1, ah2, ah3, bh0, bh1);
                mma_bf16(acc[nt], ah0, ah1, ah2, ah3, bm0, bm1);
                mma_bf16(acc[nt], am0, am1, am2, am3, bh0, bh1);
            }
        }
        if (kt < 15) {
            store_tile((kt + 1) & 1);
            __syncthreads();
        }
    }

    // epilogue: acc -> Vs (+bias)
#pragma unroll
    for (int nt = 0; nt < 4; ++nt) {
        int col = nc0 + nt * 8 + 2 * t;
        float bvl0 = bv[col], bvl1 = bv[col + 1];
        Vs[(rw + g)     * 65 + col]     = acc[nt][0] + bvl0;
        Vs[(rw + g)     * 65 + col + 1] = acc[nt][1] + bvl1;
        Vs[(rw + g + 8) * 65 + col]     = acc[nt][2] + bvl0;
        Vs[(rw + g + 8) * 65 + col + 1] = acc[nt][3] + bvl1;
    }
    __syncthreads();

    // write V
    for (int id = tid; id < 64 * 16; id += 256) {
        int r = id >> 4, fq = (id & 15) * 4;
        float4 v = make_float4(Vs[r * 65 + fq], Vs[r * 65 + fq + 1],
                               Vs[r * 65 + fq + 2], Vs[r * 65 + fq + 3]);
        *(float4*)&g_V[(size_t)(row0 + r) * 64 + fq] = v;
    }

    // Q, K projections
    int bb_ = row0 >> 11;               // batch
    int n0  = row0 & (N_ - 1);
    int r   = tid >> 2;
    int hp  = (tid & 3) * 2;
    float q0 = bq[hp], q1 = bq[hp + 1];
    float k0 = bk[hp], k1 = bk[hp + 1];
#pragma unroll 8
    for (int f = 0; f < 64; ++f) {
        float v = Vs[r * 65 + f];
        q0 += v * Wq[f * 8 + hp]; q1 += v * Wq[f * 8 + hp + 1];
        k0 += v * Wk[f * 8 + hp]; k1 += v * Wk[f * 8 + hp + 1];
    }
    int n = n0 + r;
    g_Q[(bb_ * 8 + hp) * N_ + n]     = q0;
    g_Q[(bb_ * 8 + hp + 1) * N_ + n] = q1;
    g_K[(bb_ * 8 + hp) * N_ + n]     = k0;
    g_K[(bb_ * 8 + hp + 1) * N_ + n] = k1;
}

// ------------- Kernel B1: 24-bit sort + prefix tables + records ----------
#define B1_SMEM_BYTES ((6 * 2048 + 1024 + 32 + 128 + 128 + 32 + 2) * 4)

__device__ __forceinline__ unsigned f2u_order(float f) {
    unsigned u = __float_as_uint(f);
    return u ^ ((u >> 31) ? 0xFFFFFFFFu : 0x80000000u);
}

__global__ void __launch_bounds__(1024) kernelB1()
{
    extern __shared__ __align__(16) char smemRaw[];
    unsigned* key   = (unsigned*)smemRaw;
    int*      idx   = (int*)(key + 2048);
    unsigned* key2  = (unsigned*)(idx + 2048);
    int*      idx2  = (int*)(key2 + 2048);
    float*    e1    = (float*)(idx2 + 2048);
    float*    e2    = e1 + 2048;
    int*      cnt   = (int*)(e2 + 2048);      // [16][64] digit-major
    int*      wsum  = cnt + 1024;             // 32
    float*    c1    = (float*)(wsum + 32);    // 128
    float*    c2    = c1 + 128;
    int*      bcnt  = (int*)(c2 + 128);       // 32
    float*    tots  = (float*)(bcnt + 32);    // 2
    float*    pe1s  = (float*)key2;           // reuse after sort
    float*    pe2s  = (float*)idx2;

    int bh = blockIdx.x;
    int tid = threadIdx.x;
    int lane = tid & 31;
    unsigned ltmask = (lane == 0) ? 0u : (0xFFFFFFFFu >> (32 - lane));

    for (int r = tid; r < N_; r += 1024) {
        key[r] = f2u_order(g_Q[bh * N_ + r]);
        idx[r] = r;
    }
    __syncthreads();

    // STABLE 4-bit LSD radix sort over bits [8,32): 6 passes (ends in key)
    unsigned* kin = key;  unsigned* kout = key2;
    int*      iin = idx;  int*      iout = idx2;
    int lw0 = tid >> 5, lw1 = 32 + (tid >> 5);
#pragma unroll
    for (int pass = 0; pass < 6; ++pass) {
        int shift = 8 + pass * 4;
        cnt[tid] = 0;
        __syncthreads();

        unsigned k0 = kin[tid], k1 = kin[tid + 1024];
        int      i0 = iin[tid], i1 = iin[tid + 1024];
        int d0 = (k0 >> shift) & 15, d1 = (k1 >> shift) & 15;

        unsigned m0 = __match_any_sync(0xFFFFFFFFu, d0);
        unsigned m1 = __match_any_sync(0xFFFFFFFFu, d1);
        int r0 = __popc(m0 & ltmask);
        int r1 = __popc(m1 & ltmask);
        if (r0 == 0) cnt[d0 * 64 + lw0] = __popc(m0);
        if (r1 == 0) cnt[d1 * 64 + lw1] = __popc(m1);
        __syncthreads();

        int v = cnt[tid];
        int inc = v;
#pragma unroll
        for (int off = 1; off < 32; off <<= 1) {
            int nn = __shfl_up_sync(0xFFFFFFFFu, inc, off);
            if (lane >= off) inc += nn;
        }
        if (lane == 31) wsum[tid >> 5] = inc;
        __syncthreads();
        if (tid < 32) {
            int wv = wsum[tid];
            int winc = wv;
#pragma unroll
            for (int off = 1; off < 32; off <<= 1) {
                int nn = __shfl_up_sync(0xFFFFFFFFu, winc, off);
                if (tid >= off) winc += nn;
            }
            wsum[tid] = winc - wv;   // exclusive
        }
        __syncthreads();
        cnt[tid] = inc - v + wsum[tid >> 5];   // exclusive global offset
        __syncthreads();

        int p0 = cnt[d0 * 64 + lw0] + r0;
        int p1 = cnt[d1 * 64 + lw1] + r1;
        kout[p0] = k0; iout[p0] = i0;
        kout[p1] = k1; iout[p1] = i1;
        __syncthreads();
        unsigned* tk = kin; kin = kout; kout = tk;
        int*      ti = iin; iin = iout; iout = ti;
    }

    // exp tables + publish sorted order
    for (int r = tid; r < N_; r += 1024) {
        unsigned u = key[r];
        float q = __uint_as_float(u ^ ((u >> 31) ? 0x80000000u : 0xFFFFFFFFu));
        float x1 = __expf(q), x2 = __expf(0.01f * q);
        e1[r] = x1; e2[r] = x2;
        g_si[bh * N_ + r] = idx[r];
        g_e1[bh * N_ + r] = x1;
        g_e2[bh * N_ + r] = x2;
    }
    __syncthreads();

    if (tid < 128) {
        float s1 = 0.f, s2 = 0.f;
        for (int q = 0; q < 16; ++q) { s1 += e1[tid * 16 + q]; s2 += e2[tid * 16 + q]; }
        c1[tid] = s1; c2[tid] = s2;
    }
    if (tid >= 128 && tid < 128 + NCHUNK) bcnt[tid - 128] = 0;
    __syncthreads();
    if (tid == 0) {
        float r1 = 0.f, r2 = 0.f;
        for (int q = 0; q < 128; ++q) {
            float t1 = c1[q], t2 = c2[q];
            c1[q] = r1; c2[q] = r2;
            r1 += t1; r2 += t2;
        }
        tots[0] = r1; tots[1] = r2;
    }
    __syncthreads();
    if (tid < 128) {
        float r1 = c1[tid], r2 = c2[tid];
        for (int q = 0; q < 16; ++q) {
            int r = tid * 16 + q;
            pe1s[r] = r1; pe2s[r] = r2;
            r1 += e1[r]; r2 += e2[r];
        }
    }
    __syncthreads();

    float tote1 = tots[0], tote2 = tots[1];

    // per-row records: rank via MASKED binary search
    for (int i = tid; i < N_; i += 1024) {
        float kv = g_K[bh * N_ + i];
        unsigned tu = f2u_order(-kv) & MASK24;
        int lo = 0, hi = N_;
        while (lo < hi) {
            int mid = (lo + hi) >> 1;
            if ((key[mid] & MASK24) <= tu) lo = mid + 1; else hi = mid;
        }
        float pe1 = (lo < N_) ? pe1s[lo] : tote1;
        float pe2 = (lo < N_) ? pe2s[lo] : tote2;
        float ek  = __expf(kv);
        float ek2 = __expf(0.01f * kv);
        float inv = 1.0f / (ek * (tote1 - pe1) + ek2 * pe2);
        int c = lo >> 6; if (c > NCHUNK - 1) c = NCHUNK - 1;   // t==2048 -> chunk 31
        int pos = atomicAdd(&bcnt[c], 1);
        g_rec[(bh * NCHUNK + c) * N_ + pos] =
            make_float4(__int_as_float(i), __int_as_float(lo), ek * inv, ek2 * inv);
    }
    __syncthreads();
    if (tid < NCHUNK) g_bcnt[bh * NCHUNK + tid] = bcnt[tid];
}

// ------------- Kernel P: per-(bh,chunk) partial sums, row-split ----------
__global__ void __launch_bounds__(256) kernelP()
{
    __shared__ int   sidx[CHSZ];
    __shared__ float se1[CHSZ], se2[CHSZ];
    __shared__ __align__(16) float red[8 * 128];   // [group][128 cols]

    int blk = blockIdx.x;        // 1024
    int bh  = blk >> 5;
    int g   = blk & 31;
    int b   = bh >> 3;
    int tid = threadIdx.x;
    int r0  = g * CHSZ;

    if (tid < CHSZ) {
        sidx[tid] = g_si[bh * N_ + r0 + tid];
        se1[tid]  = g_e1[bh * N_ + r0 + tid];
        se2[tid]  = g_e2[bh * N_ + r0 + tid];
    }
    __syncthreads();

    int q  = tid >> 5;           // row-group 0..7
    int f2 = tid & 31;           // column pair
    float p0 = 0.f, n0 = 0.f, p1 = 0.f, n1 = 0.f;
#pragma unroll
    for (int rr = 0; rr < 8; ++rr) {
        int r = q * 8 + rr;
        float2 v = *(const float2*)&g_V[((size_t)b * N_ + sidx[r]) * 64 + 2 * f2];
        float e1v = se1[r], e2v = se2[r];
        p0 += e1v * v.x; n0 += e2v * v.x;
        p1 += e1v * v.y; n1 += e2v * v.y;
    }
    *(float4*)&red[q * 128 + 4 * f2] = make_float4(p0, n0, p1, n1);
    __syncthreads();

    if (tid < 128) {
        float s = red[tid];
#pragma unroll
        for (int qq = 1; qq < 8; ++qq) s += red[qq * 128 + tid];
        g_part[(bh * NCHUNK + g) * 128 + tid] = s;
    }
}

// ------------- Kernel BC: fused cross-chunk scan + smem prefix + output ---
__global__ void __launch_bounds__(256) kernelBC(float* __restrict__ out)
{
    __shared__ __align__(16) float contrib[CHSZ * 128];  // 64 ranks x 128 cols (P,N)
    __shared__ __align__(16) float colEnd[128];
    __shared__ __align__(16) float sTot[128];
    __shared__ float e1s[CHSZ], e2s[CHSZ];
    __shared__ int   sidx[CHSZ];

    int blk = blockIdx.x;
    int bh  = blk >> 5;          // 0..31
    int g   = blk & 31;          // chunk
    int b   = bh >> 3, h = bh & 7;
    int tid = threadIdx.x;
    int r0  = g * CHSZ;

    float cstart = 0.f;
    if (tid < 128) {
        float v[NCHUNK];
#pragma unroll
        for (int gg = 0; gg < NCHUNK; ++gg)
            v[gg] = g_part[(bh * NCHUNK + gg) * 128 + tid];
        float tot = 0.f;
#pragma unroll
        for (int gg = 0; gg < NCHUNK; ++gg) {
            if (gg < g) cstart += v[gg];
            tot += v[gg];
        }
        sTot[tid] = tot;
    }

    if (tid >= 128 && tid < 128 + CHSZ) {
        int l = tid - 128;
        e1s[l]  = g_e1[bh * N_ + r0 + l];
        e2s[l]  = g_e2[bh * N_ + r0 + l];
        sidx[l] = g_si[bh * N_ + r0 + l];
    }
    __syncthreads();

    // gather weighted V rows: float2 loads, one STS.128 per pair
    for (int id = tid; id < CHSZ * 32; id += 256) {
        int r = id >> 5, f2 = id & 31;
        float2 v = *(const float2*)&g_V[((size_t)b * N_ + sidx[r]) * 64 + 2 * f2];
        *(float4*)&contrib[r * 128 + 4 * f2] =
            make_float4(e1s[r] * v.x, e2s[r] * v.x, e1s[r] * v.y, e2s[r] * v.y);
    }
    __syncthreads();

    if (tid < 128) {
        float run = cstart;
#pragma unroll 8
        for (int r = 0; r < CHSZ; ++r) {
            float t = contrib[r * 128 + tid];
            contrib[r * 128 + tid] = run;
            run += t;
        }
        colEnd[tid] = run;
    }
    __syncthreads();

    int base = (bh * NCHUNK + g) * N_;
    int cnt  = g_bcnt[bh * NCHUNK + g];
    int w    = tid >> 5, lane = tid & 31;

    float4 rec = make_float4(0.f, 0.f, 0.f, 0.f);
    if (w < cnt) rec = g_rec[base + w];
    for (int ii = w; ii < cnt; ii += 8) {
        float4 nrec = rec;
        if (ii + 8 < cnt) nrec = g_rec[base + ii + 8];

        int i     = __float_as_int(rec.x);
        int local = __float_as_int(rec.y) - r0;
        const float* row = (local < CHSZ) ? &contrib[local * 128] : colEnd;
        float4 c = *(const float4*)&row[lane * 4];
        float o0 = rec.z * (sTot[lane * 4 + 0] - c.x) + rec.w * c.y;
        float o1 = rec.z * (sTot[lane * 4 + 2] - c.z) + rec.w * c.w;
        *(float2*)&out[((size_t)(b * N_ + i)) * 512 + h * 64 + lane * 2] = make_float2(o0, o1);

        rec = nrec;
    }
}

// ------------- launch -----------------------------------------------------
extern "C" void kernel_launch(void* const* d_in, const int* in_sizes, int n_in,
                              void* d_out, int out_size)
{
    const float* X  = (const float*)d_in[0];
    const float* Wv = (const float*)d_in[1];
    const float* bv = (const float*)d_in[2];
    const float* Wq = (const float*)d_in[3];
    const float* bq = (const float*)d_in[4];
    const float* Wk = (const float*)d_in[5];
    const float* bk = (const float*)d_in[6];

    cudaFuncSetAttribute(kernelA,  cudaFuncAttributeMaxDynamicSharedMemorySize, SMEMA_BYTES);
    cudaFuncSetAttribute(kernelB1, cudaFuncAttributeMaxDynamicSharedMemorySize, B1_SMEM_BYTES);

    kernelW<<<64, 256>>>(Wv);
    kernelA<<<(B_ * N_) / 64, 256, SMEMA_BYTES>>>(X, bv, Wq, bq, Wk, bk);
    kernelB1<<<BH_, 1024, B1_SMEM_BYTES>>>();
    kernelP<<<BH_ * NCHUNK, 256>>>();
    kernelBC<<<BH_ * NCHUNK, 256>>>((float*)d_out);
}